// round 14
// baseline (speedup 1.0000x reference)
#include <cuda_runtime.h>
#include <cuda_fp16.h>

// ---------------------------------------------------------------------------
// Popcnt_14731737825611 — R9: fp16 warp-uniform gathers + bucket-ordered
// pair tables for L1 reuse.
// Warp = 1 output; lanes cover 8 batch columns (coalesced 512B row reads).
// Each output's 128 (idx, w) pairs are grouped by row-index bucket (64-128KB
// of rows per bucket) so all concurrent warps sweep the activation table in
// the same coarse order -> shared L1-resident working set, less LTS traffic.
// LN folded via C1/C2; LN partials fused into pop epilogue; coalesced k_fin;
// final group-sum fused into pop3. 7 launches.
// ---------------------------------------------------------------------------

namespace {
constexpr int B     = 256;
constexpr int IN1   = 3200;
constexpr int O1    = 8192;
constexpr int O3    = 4096;
constexpr int P     = 128;
constexpr int NSLOT = O1 / 8;     // 1024 partial slots (pop1/pop2 CTA count)
}

// Static device scratch.
__device__ __half g_xT[IN1 * B];
__device__ __half g_h1[O1 * B];
__device__ __half g_h2[O1 * B];
__device__ uint4  g_pk1[O1 * 32];
__device__ uint4  g_pk2[O1 * 32];
__device__ uint4  g_pk3[O3 * 32];
__device__ float  g_C1b[O1], g_C2b[O1], g_C1c[O3], g_C2c[O3];
__device__ float  g_ps[NSLOT * B], g_pq[NSLOT * B];
__device__ float  g_mu[2][B], g_rs[2][B];

__device__ __forceinline__ float sigmoidf_fast(float x) {
    return 1.0f / (1.0f + __expf(-x));
}
__device__ __forceinline__ unsigned pack_pair(int idx, float w) {
    __half h = __float2half_rn(w);
    return (unsigned)idx | ((unsigned)__half_as_ushort(h) << 16);
}
__device__ __forceinline__ float wgt(unsigned pc) {
    return __half2float(__ushort_as_half((unsigned short)(pc >> 16)));
}
__device__ __forceinline__ void fma8(const uint4 v, const float wv, float* acc) {
    float2 f;
    f = __half22float2(*(const __half2*)&v.x); acc[0] = fmaf(wv, f.x, acc[0]); acc[1] = fmaf(wv, f.y, acc[1]);
    f = __half22float2(*(const __half2*)&v.y); acc[2] = fmaf(wv, f.x, acc[2]); acc[3] = fmaf(wv, f.y, acc[3]);
    f = __half22float2(*(const __half2*)&v.z); acc[4] = fmaf(wv, f.x, acc[4]); acc[5] = fmaf(wv, f.y, acc[5]);
    f = __half22float2(*(const __half2*)&v.w); acc[6] = fmaf(wv, f.x, acc[6]); acc[7] = fmaf(wv, f.y, acc[7]);
}
__device__ __forceinline__ uint4 pack_h8(const float* h) {
    uint4 ov; __half2 hh;
    hh = __floats2half2_rn(h[0], h[1]); ov.x = *(unsigned*)&hh;
    hh = __floats2half2_rn(h[2], h[3]); ov.y = *(unsigned*)&hh;
    hh = __floats2half2_rn(h[4], h[5]); ov.z = *(unsigned*)&hh;
    hh = __floats2half2_rn(h[6], h[7]); ov.w = *(unsigned*)&hh;
    return ov;
}

// --- transpose x[B, IN1] -> g_xT[IN1, B] (fp16) ----------------------------
__global__ void k_transpose(const float* __restrict__ x) {
    __shared__ float t[32][33];
    const int i0 = blockIdx.x * 32;
    const int b0 = blockIdx.y * 32;
    const int tx = threadIdx.x, ty = threadIdx.y;
#pragma unroll
    for (int j = 0; j < 32; j += 8)
        t[ty + j][tx] = x[(b0 + ty + j) * IN1 + (i0 + tx)];
    __syncthreads();
#pragma unroll
    for (int j = 0; j < 32; j += 8)
        g_xT[(i0 + ty + j) * B + (b0 + tx)] = __float2half_rn(t[tx][ty + j]);
}

// --- merged prep: pack pair tables grouped by row bucket; C1/C2 ------------
// Warp = 1 output. Deterministic warp counting-sort by bucket (match_any).
__global__ void __launch_bounds__(256) k_prep(
    const int* __restrict__ sel1, const float* __restrict__ w1,
    const int* __restrict__ sel2, const float* __restrict__ w2,
    const float* __restrict__ g1v, const float* __restrict__ be1,
    const int* __restrict__ sel3, const float* __restrict__ w3,
    const float* __restrict__ g2v, const float* __restrict__ be2)
{
    __shared__ unsigned stage[8][128];
    __shared__ int      roff[8][32];

    const int gw   = blockIdx.x * 8 + (threadIdx.x >> 5);
    const int wslt = threadIdx.x >> 5;
    const int lane = threadIdx.x & 31;

    int layer, o;
    const int* sel; const float* w; const float* gm; const float* bt;
    uint4* pk; float* C1; float* C2;
    if (gw < O1)           { layer = 1; o = gw;          sel = sel1; w = w1; gm = nullptr; bt = nullptr; pk = g_pk1; C1 = nullptr; C2 = nullptr; }
    else if (gw < 2 * O1)  { layer = 2; o = gw - O1;     sel = sel2; w = w2; gm = g1v;    bt = be1;     pk = g_pk2; C1 = g_C1b;  C2 = g_C2b; }
    else                   { layer = 3; o = gw - 2 * O1; sel = sel3; w = w3; gm = g2v;    bt = be2;     pk = g_pk3; C1 = g_C1c;  C2 = g_C2c; }
    const int SH = (layer == 1) ? 7 : 8;        // <=25 / 32 buckets

    const int4   s4 = reinterpret_cast<const int4*>(sel + o * P)[lane];
    const float4 w4 = reinterpret_cast<const float4*>(w   + o * P)[lane];
    const int   idx[4] = { s4.x, s4.y, s4.z, s4.w };
    const float sg[4]  = { sigmoidf_fast(w4.x), sigmoidf_fast(w4.y),
                           sigmoidf_fast(w4.z), sigmoidf_fast(w4.w) };
    unsigned pc[4]; int bk[4];
    float c1 = 0.f, c2 = 0.f;
#pragma unroll
    for (int j = 0; j < 4; ++j) {
        float sw = sg[j];
        if (layer > 1) {
            sw *= __ldg(gm + idx[j]);
            c1 += sw;
            c2 = fmaf(sg[j], __ldg(bt + idx[j]), c2);
        }
        pc[j] = pack_pair(idx[j], sw);
        bk[j] = idx[j] >> SH;
    }
    if (layer > 1) {
#pragma unroll
        for (int st = 16; st > 0; st >>= 1) {
            c1 += __shfl_xor_sync(0xffffffffu, c1, st);
            c2 += __shfl_xor_sync(0xffffffffu, c2, st);
        }
        if (lane == 0) { C1[o] = c1; C2[o] = c2; }
    }

    // -- counting sort by bucket (deterministic: rank by (reg, lane)) --
    roff[wslt][lane] = 0;
    __syncwarp();
#pragma unroll
    for (int j = 0; j < 4; ++j) {
        const unsigned m = __match_any_sync(0xffffffffu, bk[j]);
        if (lane == (__ffs(m) - 1)) roff[wslt][bk[j]] += __popc(m);
        __syncwarp();
    }
    {   // exclusive scan of counts -> bucket bases
        const int cnt = roff[wslt][lane];
        int sc = cnt;
#pragma unroll
        for (int st = 1; st < 32; st <<= 1) {
            const int t = __shfl_up_sync(0xffffffffu, sc, st);
            if (lane >= st) sc += t;
        }
        __syncwarp();
        roff[wslt][lane] = sc - cnt;
    }
    __syncwarp();
#pragma unroll
    for (int j = 0; j < 4; ++j) {
        const unsigned m  = __match_any_sync(0xffffffffu, bk[j]);
        const int      lt = __popc(m & ((1u << lane) - 1u));
        const int      pos = roff[wslt][bk[j]] + lt;
        __syncwarp();
        if (lane == (__ffs(m) - 1)) roff[wslt][bk[j]] += __popc(m);
        __syncwarp();
        stage[wslt][pos] = pc[j];
    }
    __syncwarp();
    uint4 qv;
    qv.x = stage[wslt][lane * 4 + 0];
    qv.y = stage[wslt][lane * 4 + 1];
    qv.z = stage[wslt][lane * 4 + 2];
    qv.w = stage[wslt][lane * 4 + 3];
    pk[o * 32 + lane] = qv;
}

// --- popcnt layer: warp = 1 output, lane = 8 batch columns -----------------
template <int L>
__global__ void __launch_bounds__((L == 3) ? 512 : 256) k_pop(
    const float* __restrict__ bias, float* __restrict__ out)
{
    constexpr int WARPS = (L == 3) ? 16 : 8;
    __shared__ float sh[WARPS][B];

    const __half* inT  = (L == 1) ? g_xT  : (L == 2) ? g_h1  : g_h2;
    const uint4*  pk   = (L == 1) ? g_pk1 : (L == 2) ? g_pk2 : g_pk3;
    __half*       outT = (L == 1) ? g_h1  : g_h2;

    const int tid  = threadIdx.x;
    const int wid  = tid >> 5;
    const int lane = tid & 31;
    const int o    = blockIdx.x * WARPS + wid;

    const uint4* pq = pk + o * 32;
    uint4 qd = __ldg(pq);
    float acc[8];
#pragma unroll
    for (int j = 0; j < 8; ++j) acc[j] = 0.f;

#pragma unroll 4
    for (int q = 0; q < 32; ++q) {
        const uint4 qn = __ldg(pq + ((q + 1) & 31));
        const unsigned p0 = qd.x, p1 = qd.y, p2 = qd.z, p3 = qd.w;
        const uint4 v0 = *(reinterpret_cast<const uint4*>(inT + (p0 & 0xFFFFu) * B) + lane);
        const uint4 v1 = *(reinterpret_cast<const uint4*>(inT + (p1 & 0xFFFFu) * B) + lane);
        const uint4 v2 = *(reinterpret_cast<const uint4*>(inT + (p2 & 0xFFFFu) * B) + lane);
        const uint4 v3 = *(reinterpret_cast<const uint4*>(inT + (p3 & 0xFFFFu) * B) + lane);
        fma8(v0, wgt(p0), acc);
        fma8(v1, wgt(p1), acc);
        fma8(v2, wgt(p2), acc);
        fma8(v3, wgt(p3), acc);
        qd = qn;
    }

    // epilogue: (folded input-LN) + bias + sigmoid
    const float bo = __ldg(bias + o);
    float h[8];
    if (L > 1) {
        const float c1  = ((L == 2) ? g_C1b : g_C1c)[o];
        const float c2v = ((L == 2) ? g_C2b : g_C2c)[o];
        const float4 mA = *reinterpret_cast<const float4*>(&g_mu[L - 2][lane * 8]);
        const float4 mB = *reinterpret_cast<const float4*>(&g_mu[L - 2][lane * 8 + 4]);
        const float4 rA = *reinterpret_cast<const float4*>(&g_rs[L - 2][lane * 8]);
        const float4 rB = *reinterpret_cast<const float4*>(&g_rs[L - 2][lane * 8 + 4]);
        const float mu[8] = { mA.x, mA.y, mA.z, mA.w, mB.x, mB.y, mB.z, mB.w };
        const float rs[8] = { rA.x, rA.y, rA.z, rA.w, rB.x, rB.y, rB.z, rB.w };
#pragma unroll
        for (int j = 0; j < 8; ++j)
            h[j] = sigmoidf_fast(fmaf(rs[j], acc[j] - mu[j] * c1, c2v) - bo);
    } else {
#pragma unroll
        for (int j = 0; j < 8; ++j)
            h[j] = sigmoidf_fast(acc[j] - bo);
    }

    if (L < 3) {
        *(reinterpret_cast<uint4*>(outT + o * B) + lane) = pack_h8(h);
#pragma unroll
        for (int j = 0; j < 8; ++j) sh[wid][lane * 8 + j] = h[j];
        __syncthreads();
        {
            float s = 0.f, qv = 0.f;
#pragma unroll
            for (int w = 0; w < WARPS; ++w) {
                const float v = sh[w][tid];
                s += v;
                qv = fmaf(v, v, qv);
            }
            g_ps[blockIdx.x * B + tid] = s;
            g_pq[blockIdx.x * B + tid] = qv;
        }
    } else {
        // fused final: this block IS one output group of 16
#pragma unroll
        for (int j = 0; j < 8; ++j) sh[wid][lane * 8 + j] = h[j];
        __syncthreads();
        if (tid < B) {
            float s = 0.f;
#pragma unroll
            for (int w = 0; w < 16; ++w) s += sh[w][tid];
            out[tid * 256 + blockIdx.x] = s - 8.0f;
        }
    }
}

// --- LN finalize, coalesced: block = 32 cols x 32 slot-lanes ---------------
template <int LI>
__global__ void __launch_bounds__(1024) k_fin() {
    __shared__ float ss[32][33], sq[32][33];
    const int c   = threadIdx.x & 31;          // col within group (coalesced)
    const int s   = threadIdx.x >> 5;          // slot lane
    const int col = blockIdx.x * 32 + c;
    float sv = 0.f, qv = 0.f;
    for (int k = s; k < NSLOT; k += 32) {
        sv += g_ps[k * B + col];
        qv += g_pq[k * B + col];
    }
    ss[s][c] = sv; sq[s][c] = qv;
    __syncthreads();
    for (int st = 16; st > 0; st >>= 1) {
        if (s < st) { ss[s][c] += ss[s + st][c]; sq[s][c] += sq[s + st][c]; }
        __syncthreads();
    }
    if (s == 0) {
        const float inv = 1.0f / (float)O1;
        const float m   = ss[0][c] * inv;
        const float var = sq[0][c] * inv - m * m;
        g_mu[LI][col] = m;
        g_rs[LI][col] = rsqrtf(var + 1e-12f);
    }
}

// ---------------------------------------------------------------------------
extern "C" void kernel_launch(void* const* d_in, const int* in_sizes, int n_in,
                              void* d_out, int out_size) {
    (void)in_sizes; (void)n_in; (void)out_size;
    const float* x    = (const float*)d_in[0];
    const int*   sel1 = (const int*)  d_in[1];
    const float* w1   = (const float*)d_in[2];
    const float* b1   = (const float*)d_in[3];
    const float* g1   = (const float*)d_in[4];
    const float* be1  = (const float*)d_in[5];
    const int*   sel2 = (const int*)  d_in[6];
    const float* w2   = (const float*)d_in[7];
    const float* b2   = (const float*)d_in[8];
    const float* g2   = (const float*)d_in[9];
    const float* be2  = (const float*)d_in[10];
    const int*   sel3 = (const int*)  d_in[11];
    const float* w3   = (const float*)d_in[12];
    const float* b3   = (const float*)d_in[13];
    float* out = (float*)d_out;

    k_transpose<<<dim3(IN1 / 32, B / 32), dim3(32, 8)>>>(x);
    k_prep<<<(2 * O1 + O3) / 8, 256>>>(sel1, w1, sel2, w2, g1, be1,
                                       sel3, w3, g2, be2);

    k_pop<1><<<O1 / 8, 256>>>(b1, nullptr);
    k_fin<0><<<B / 32, 1024>>>();
    k_pop<2><<<O1 / 8, 256>>>(b2, nullptr);
    k_fin<1><<<B / 32, 1024>>>();
    k_pop<3><<<O3 / 16, 512>>>(b3, out);
}

// round 15
// speedup vs baseline: 1.1067x; 1.1067x over previous
#include <cuda_runtime.h>
#include <cuda_fp16.h>

// ---------------------------------------------------------------------------
// Popcnt_14731737825611 — R10: R7 architecture + transposed LN partials +
// merged setup kernel.
// Warp = 1 output; lanes cover 8 batch columns (warp-uniform row gathers at
// the LTS ceiling). Pair tables uint4 quads (u16 idx | fp16 w). LN folded
// via C1/C2; LN partials written [col][slot] (coalesced finalize); final
// group-sum fused into pop3. 6 launches.
// ---------------------------------------------------------------------------

namespace {
constexpr int B     = 256;
constexpr int IN1   = 3200;
constexpr int O1    = 8192;
constexpr int O3    = 4096;
constexpr int P     = 128;
constexpr int NSLOT = O1 / 8;          // 1024 partial slots (pop1/pop2 CTAs)
constexpr int PREPB = (2 * O1 + O3) / 8;   // 2560 prep blocks
constexpr int TRB   = (IN1 / 32) * (B / 32); // 800 transpose blocks
}

// Static device scratch.
__device__ __half g_xT[IN1 * B];
__device__ __half g_h1[O1 * B];
__device__ __half g_h2[O1 * B];
__device__ uint4  g_pk1[O1 * 32];
__device__ uint4  g_pk2[O1 * 32];
__device__ uint4  g_pk3[O3 * 32];
__device__ float  g_C1b[O1], g_C2b[O1], g_C1c[O3], g_C2c[O3];
__device__ float  g_psT[B * NSLOT], g_pqT[B * NSLOT];   // [col][slot]
__device__ float  g_mu[2][B], g_rs[2][B];

__device__ __forceinline__ float sigmoidf_fast(float x) {
    return 1.0f / (1.0f + __expf(-x));
}
__device__ __forceinline__ unsigned pack_pair(int idx, float w) {
    __half h = __float2half_rn(w);
    return (unsigned)idx | ((unsigned)__half_as_ushort(h) << 16);
}
__device__ __forceinline__ float wgt(unsigned pc) {
    return __half2float(__ushort_as_half((unsigned short)(pc >> 16)));
}
__device__ __forceinline__ void fma8(const uint4 v, const float wv, float* acc) {
    float2 f;
    f = __half22float2(*(const __half2*)&v.x); acc[0] = fmaf(wv, f.x, acc[0]); acc[1] = fmaf(wv, f.y, acc[1]);
    f = __half22float2(*(const __half2*)&v.y); acc[2] = fmaf(wv, f.x, acc[2]); acc[3] = fmaf(wv, f.y, acc[3]);
    f = __half22float2(*(const __half2*)&v.z); acc[4] = fmaf(wv, f.x, acc[4]); acc[5] = fmaf(wv, f.y, acc[5]);
    f = __half22float2(*(const __half2*)&v.w); acc[6] = fmaf(wv, f.x, acc[6]); acc[7] = fmaf(wv, f.y, acc[7]);
}
__device__ __forceinline__ uint4 pack_h8(const float* h) {
    uint4 ov; __half2 hh;
    hh = __floats2half2_rn(h[0], h[1]); ov.x = *(unsigned*)&hh;
    hh = __floats2half2_rn(h[2], h[3]); ov.y = *(unsigned*)&hh;
    hh = __floats2half2_rn(h[4], h[5]); ov.z = *(unsigned*)&hh;
    hh = __floats2half2_rn(h[6], h[7]); ov.w = *(unsigned*)&hh;
    return ov;
}

// --- merged setup: blocks [0, PREPB) pack pair tables + C1/C2;
//     blocks [PREPB, PREPB+TRB) transpose x -> g_xT (fp16). --------------
__global__ void __launch_bounds__(256) k_setup(
    const float* __restrict__ x,
    const int* __restrict__ sel1, const float* __restrict__ w1,
    const int* __restrict__ sel2, const float* __restrict__ w2,
    const float* __restrict__ g1v, const float* __restrict__ be1,
    const int* __restrict__ sel3, const float* __restrict__ w3,
    const float* __restrict__ g2v, const float* __restrict__ be2)
{
    const int blk = blockIdx.x;
    if (blk >= PREPB) {
        // ---- transpose tile ----
        __shared__ float t[32][33];
        const int tb = blk - PREPB;
        const int i0 = (tb % (IN1 / 32)) * 32;
        const int b0 = (tb / (IN1 / 32)) * 32;
        const int tx = threadIdx.x & 31, ty = threadIdx.x >> 5;  // ty 0..7
#pragma unroll
        for (int j = 0; j < 32; j += 8)
            t[ty + j][tx] = x[(b0 + ty + j) * IN1 + (i0 + tx)];
        __syncthreads();
#pragma unroll
        for (int j = 0; j < 32; j += 8)
            g_xT[(i0 + ty + j) * B + (b0 + tx)] = __float2half_rn(t[tx][ty + j]);
        return;
    }

    // ---- prep: warp = 1 output ----
    const int gw   = blk * 8 + (threadIdx.x >> 5);
    const int lane = threadIdx.x & 31;

    int layer, o;
    const int* sel; const float* w; const float* gm; const float* bt;
    uint4* pk; float* C1; float* C2;
    if (gw < O1)           { layer = 1; o = gw;          sel = sel1; w = w1; gm = nullptr; bt = nullptr; pk = g_pk1; C1 = nullptr; C2 = nullptr; }
    else if (gw < 2 * O1)  { layer = 2; o = gw - O1;     sel = sel2; w = w2; gm = g1v;    bt = be1;     pk = g_pk2; C1 = g_C1b;  C2 = g_C2b; }
    else                   { layer = 3; o = gw - 2 * O1; sel = sel3; w = w3; gm = g2v;    bt = be2;     pk = g_pk3; C1 = g_C1c;  C2 = g_C2c; }

    const int4   s4 = reinterpret_cast<const int4*>(sel + o * P)[lane];
    const float4 w4 = reinterpret_cast<const float4*>(w   + o * P)[lane];
    const int   idx[4] = { s4.x, s4.y, s4.z, s4.w };
    const float sg[4]  = { sigmoidf_fast(w4.x), sigmoidf_fast(w4.y),
                           sigmoidf_fast(w4.z), sigmoidf_fast(w4.w) };
    unsigned pc[4];
    float c1 = 0.f, c2 = 0.f;
#pragma unroll
    for (int j = 0; j < 4; ++j) {
        float sw = sg[j];
        if (layer > 1) {
            sw *= __ldg(gm + idx[j]);
            c1 += sw;
            c2 = fmaf(sg[j], __ldg(bt + idx[j]), c2);
        }
        pc[j] = pack_pair(idx[j], sw);
    }
    pk[o * 32 + lane] = make_uint4(pc[0], pc[1], pc[2], pc[3]);
    if (layer > 1) {
#pragma unroll
        for (int st = 16; st > 0; st >>= 1) {
            c1 += __shfl_xor_sync(0xffffffffu, c1, st);
            c2 += __shfl_xor_sync(0xffffffffu, c2, st);
        }
        if (lane == 0) { C1[o] = c1; C2[o] = c2; }
    }
}

// --- popcnt layer: warp = 1 output, lane = 8 batch columns -----------------
// L=1,2: block 256 (8 warps), grid O1/8; fused LN partial per CTA.
// L=3:   block 512 (16 warps = one output group), grid O3/16; fused final.
template <int L>
__global__ void __launch_bounds__((L == 3) ? 512 : 256) k_pop(
    const float* __restrict__ bias, float* __restrict__ out)
{
    constexpr int WARPS = (L == 3) ? 16 : 8;
    __shared__ float sh[WARPS][B];

    const __half* inT  = (L == 1) ? g_xT  : (L == 2) ? g_h1  : g_h2;
    const uint4*  pk   = (L == 1) ? g_pk1 : (L == 2) ? g_pk2 : g_pk3;
    __half*       outT = (L == 1) ? g_h1  : g_h2;

    const int tid  = threadIdx.x;
    const int wid  = tid >> 5;
    const int lane = tid & 31;
    const int o    = blockIdx.x * WARPS + wid;

    const uint4* pq = pk + o * 32;
    uint4 qd = __ldg(pq);
    float acc[8];
#pragma unroll
    for (int j = 0; j < 8; ++j) acc[j] = 0.f;

#pragma unroll 4
    for (int q = 0; q < 32; ++q) {
        const uint4 qn = __ldg(pq + ((q + 1) & 31));
        const unsigned p0 = qd.x, p1 = qd.y, p2 = qd.z, p3 = qd.w;
        const uint4 v0 = *(reinterpret_cast<const uint4*>(inT + (p0 & 0xFFFFu) * B) + lane);
        const uint4 v1 = *(reinterpret_cast<const uint4*>(inT + (p1 & 0xFFFFu) * B) + lane);
        const uint4 v2 = *(reinterpret_cast<const uint4*>(inT + (p2 & 0xFFFFu) * B) + lane);
        const uint4 v3 = *(reinterpret_cast<const uint4*>(inT + (p3 & 0xFFFFu) * B) + lane);
        fma8(v0, wgt(p0), acc);
        fma8(v1, wgt(p1), acc);
        fma8(v2, wgt(p2), acc);
        fma8(v3, wgt(p3), acc);
        qd = qn;
    }

    // epilogue: (folded input-LN) + bias + sigmoid
    const float bo = __ldg(bias + o);
    float h[8];
    if (L > 1) {
        const float c1  = ((L == 2) ? g_C1b : g_C1c)[o];
        const float c2v = ((L == 2) ? g_C2b : g_C2c)[o];
        const float4 mA = *reinterpret_cast<const float4*>(&g_mu[L - 2][lane * 8]);
        const float4 mB = *reinterpret_cast<const float4*>(&g_mu[L - 2][lane * 8 + 4]);
        const float4 rA = *reinterpret_cast<const float4*>(&g_rs[L - 2][lane * 8]);
        const float4 rB = *reinterpret_cast<const float4*>(&g_rs[L - 2][lane * 8 + 4]);
        const float mu[8] = { mA.x, mA.y, mA.z, mA.w, mB.x, mB.y, mB.z, mB.w };
        const float rs[8] = { rA.x, rA.y, rA.z, rA.w, rB.x, rB.y, rB.z, rB.w };
#pragma unroll
        for (int j = 0; j < 8; ++j)
            h[j] = sigmoidf_fast(fmaf(rs[j], acc[j] - mu[j] * c1, c2v) - bo);
    } else {
#pragma unroll
        for (int j = 0; j < 8; ++j)
            h[j] = sigmoidf_fast(acc[j] - bo);
    }

    if (L < 3) {
        *(reinterpret_cast<uint4*>(outT + o * B) + lane) = pack_h8(h);
#pragma unroll
        for (int j = 0; j < 8; ++j) sh[wid][lane * 8 + j] = h[j];
        __syncthreads();
        {
            float s = 0.f, qv = 0.f;
#pragma unroll
            for (int w = 0; w < WARPS; ++w) {
                const float v = sh[w][tid];
                s += v;
                qv = fmaf(v, v, qv);
            }
            // transposed partials: [col][slot] -> coalesced finalize reads
            g_psT[tid * NSLOT + blockIdx.x] = s;
            g_pqT[tid * NSLOT + blockIdx.x] = qv;
        }
    } else {
        // fused final: this block IS one output group of 16
#pragma unroll
        for (int j = 0; j < 8; ++j) sh[wid][lane * 8 + j] = h[j];
        __syncthreads();
        if (tid < B) {
            float s = 0.f;
#pragma unroll
            for (int w = 0; w < 16; ++w) s += sh[w][tid];
            out[tid * 256 + blockIdx.x] = s - 8.0f;
        }
    }
}

// --- LN finalize: block per column, fully coalesced ------------------------
template <int LI>
__global__ void __launch_bounds__(256) k_fin() {
    __shared__ float ss[256], sq[256];
    const int col = blockIdx.x;
    const int t   = threadIdx.x;
    const float* ps = g_psT + col * NSLOT;
    const float* pq = g_pqT + col * NSLOT;
    float s = 0.f, q = 0.f;
#pragma unroll
    for (int k = 0; k < NSLOT / 256; ++k) {
        s += ps[t + k * 256];
        q += pq[t + k * 256];
    }
    ss[t] = s; sq[t] = q;
    __syncthreads();
    for (int st = 128; st > 0; st >>= 1) {
        if (t < st) { ss[t] += ss[t + st]; sq[t] += sq[t + st]; }
        __syncthreads();
    }
    if (t == 0) {
        const float inv = 1.0f / (float)O1;
        const float m   = ss[0] * inv;
        const float var = sq[0] * inv - m * m;
        g_mu[LI][col] = m;
        g_rs[LI][col] = rsqrtf(var + 1e-12f);
    }
}

// ---------------------------------------------------------------------------
extern "C" void kernel_launch(void* const* d_in, const int* in_sizes, int n_in,
                              void* d_out, int out_size) {
    (void)in_sizes; (void)n_in; (void)out_size;
    const float* x    = (const float*)d_in[0];
    const int*   sel1 = (const int*)  d_in[1];
    const float* w1   = (const float*)d_in[2];
    const float* b1   = (const float*)d_in[3];
    const float* g1   = (const float*)d_in[4];
    const float* be1  = (const float*)d_in[5];
    const int*   sel2 = (const int*)  d_in[6];
    const float* w2   = (const float*)d_in[7];
    const float* b2   = (const float*)d_in[8];
    const float* g2   = (const float*)d_in[9];
    const float* be2  = (const float*)d_in[10];
    const int*   sel3 = (const int*)  d_in[11];
    const float* w3   = (const float*)d_in[12];
    const float* b3   = (const float*)d_in[13];
    float* out = (float*)d_out;

    k_setup<<<PREPB + TRB, 256>>>(x, sel1, w1, sel2, w2, g1, be1,
                                  sel3, w3, g2, be2);

    k_pop<1><<<O1 / 8, 256>>>(b1, nullptr);
    k_fin<0><<<B, 256>>>();
    k_pop<2><<<O1 / 8, 256>>>(b2, nullptr);
    k_fin<1><<<B, 256>>>();
    k_pop<3><<<O3 / 16, 512>>>(b3, out);
}